// round 2
// baseline (speedup 1.0000x reference)
#include <cuda_runtime.h>
#include <cuda_bf16.h>

// CenterLoss collapses analytically:
//   loss = ( sum_i clip(||x_i||^2 + ||c_{l_i}||^2 - 2 x_i . c_{l_i}, 1e-12, 1e12)
//            + B*(C-1)*1e-12 ) / B
// Only the 1024 gathered label-center rows are needed; the BxC distmat never exists.
// Work: ~2 MB reads, ~0.8 MFLOP -> launch-latency bound.

#define B_ROWS 1024
#define D_DIM  256
#define C_CLS  100000

static __device__ float g_row_dist[B_ROWS];
static __device__ int   g_lab_is_i64;   // 1 if labels buffer is int64, 0 if int32

// Kernel 0: detect label dtype. Interpret the first 4KB (always in-bounds:
// 1024 int32 = 4KB, 1024 int64 = 8KB) as 512 int64s. Real int64 labels are all
// in [0, C); int32 data viewed as int64 = lo + (hi<<32), which is >= 2^32
// unless hi (a label) == 0 -- 512 consecutive zeros is impossible for random labels.
__global__ void detect_label_dtype_kernel(const void* __restrict__ labels_raw) {
    const long long* p = (const long long*)labels_raw;
    int ok = 1;
    for (int i = 0; i < 512; i++) {
        long long v = p[i];
        if (v < 0 || v >= (long long)C_CLS) { ok = 0; break; }
    }
    g_lab_is_i64 = ok;
}

// Kernel 1: one block per row, one thread per dim.
// d_i = sum_t ( x[t]^2 + c[t]^2 - 2 x[t] c[t] )  in fp32, fixed reduction order.
__global__ void center_row_dist_kernel(const float* __restrict__ x,
                                       const void* __restrict__ labels_raw,
                                       const float* __restrict__ centers) {
    const int row = blockIdx.x;
    const int t   = threadIdx.x;          // 0..255

    long long lab;
    if (g_lab_is_i64) {
        lab = ((const long long*)labels_raw)[row];
    } else {
        lab = (long long)((const int*)labels_raw)[row];
    }
    // safety clamp: never OOB even if detection were wrong
    if (lab < 0) lab = 0;
    if (lab >= C_CLS) lab = C_CLS - 1;

    const float xv = x[(size_t)row * D_DIM + t];
    const float cv = centers[(size_t)lab * D_DIM + t];
    const float d  = xv - cv;
    // (x-c)^2 == x^2 + c^2 - 2xc exactly in the reference's algebra; fp32
    // rounding differences are ~1e-7 relative, far below the 1e-3 gate.
    float term = d * d;

    #pragma unroll
    for (int off = 16; off > 0; off >>= 1)
        term += __shfl_xor_sync(0xFFFFFFFFu, term, off);

    __shared__ float s_warp[8];
    const int lane = t & 31;
    const int wid  = t >> 5;
    if (lane == 0) s_warp[wid] = term;
    __syncthreads();

    if (wid == 0) {
        float v = (lane < 8) ? s_warp[lane] : 0.0f;
        #pragma unroll
        for (int off = 4; off > 0; off >>= 1)
            v += __shfl_xor_sync(0xFFFFFFFFu, v, off);
        if (lane == 0) g_row_dist[row] = v;
    }
}

// Kernel 2: single block, deterministic reduction of the 1024 row distances.
__global__ void center_finalize_kernel(float* __restrict__ out) {
    const int t = threadIdx.x;             // 0..1023

    float d = g_row_dist[t];
    d = fminf(fmaxf(d, 1e-12f), 1e12f);
    double acc = (double)d;

    #pragma unroll
    for (int off = 16; off > 0; off >>= 1)
        acc += __shfl_xor_sync(0xFFFFFFFFu, acc, off);

    __shared__ double s_warp[32];
    const int lane = t & 31;
    const int wid  = t >> 5;
    if (lane == 0) s_warp[wid] = acc;
    __syncthreads();

    if (wid == 0) {
        double v = s_warp[lane];
        #pragma unroll
        for (int off = 16; off > 0; off >>= 1)
            v += __shfl_xor_sync(0xFFFFFFFFu, v, off);
        if (lane == 0) {
            const double floor_term = (double)B_ROWS * (double)(C_CLS - 1) * 1e-12;
            out[0] = (float)((v + floor_term) / (double)B_ROWS);
        }
    }
}

extern "C" void kernel_launch(void* const* d_in, const int* in_sizes, int n_in,
                              void* d_out, int out_size) {
    // Identify inputs by element count (robust to ordering):
    //   x: 1024*256 = 262144, labels: 1024, centers: 100000*256 = 25600000
    const float* x       = nullptr;
    const void*  labels  = nullptr;
    const float* centers = nullptr;
    for (int i = 0; i < n_in; i++) {
        if (in_sizes[i] == B_ROWS * D_DIM)      x       = (const float*)d_in[i];
        else if (in_sizes[i] == B_ROWS)         labels  = d_in[i];
        else if (in_sizes[i] == C_CLS * D_DIM)  centers = (const float*)d_in[i];
    }
    float* out = (float*)d_out;

    detect_label_dtype_kernel<<<1, 1>>>(labels);
    center_row_dist_kernel<<<B_ROWS, D_DIM>>>(x, labels, centers);
    center_finalize_kernel<<<1, B_ROWS>>>(out);
}

// round 3
// speedup vs baseline: 1.2007x; 1.2007x over previous
#include <cuda_runtime.h>
#include <cuda_bf16.h>

// CenterLoss collapses analytically:
//   loss = ( sum_i clip(||x_i - c_{l_i}||^2, 1e-12, 1e12) + B*(C-1)*1e-12 ) / B
// Single fused kernel: warp-per-row gather+reduce, last-block-done finalize.

#define B_ROWS 1024
#define D_DIM  256
#define C_CLS  100000

#define THREADS 256               // 8 warps = 8 rows per block
#define BLOCKS  (B_ROWS / 8)      // 128

static __device__ float        g_row_dist[B_ROWS];
static __device__ unsigned int g_done = 0;   // reset to 0 by final block each call

__global__ void __launch_bounds__(THREADS)
center_loss_fused_kernel(const float* __restrict__ x,
                         const void*  __restrict__ labels_raw,
                         const float* __restrict__ centers,
                         float* __restrict__ out) {
    const int tid  = threadIdx.x;
    const int lane = tid & 31;
    const int warp = tid >> 5;                 // 0..7
    const int row  = blockIdx.x * 8 + warp;    // 0..1023

    // ---- inline label-dtype detection (uniform, 32B read, L2 broadcast) ----
    // labels buffer is >= 4KB; reading first 4 int64 (32B) is always in-bounds.
    // Genuine int64 labels are all in [0,C). int32 data viewed as int64 is
    // lo | hi<<32 >= 2^32 unless hi==0; 4 consecutive zero-high-halves is
    // vanishingly unlikely for random labels.
    const long long* p64 = (const long long*)labels_raw;
    bool is64 = true;
    #pragma unroll
    for (int i = 0; i < 4; i++) {
        long long v = p64[i];
        if (v < 0 || v >= (long long)C_CLS) is64 = false;
    }

    long long lab = is64 ? p64[row]
                         : (long long)((const int*)labels_raw)[row];
    if (lab < 0) lab = 0;                      // safety: never OOB
    if (lab >= C_CLS) lab = C_CLS - 1;

    // ---- per-row squared distance: 256 dims, warp of 32 lanes, float4 x2 ----
    const float4* xr = (const float4*)(x + (size_t)row * D_DIM);
    const float4* cr = (const float4*)(centers + (size_t)lab * D_DIM);

    float4 xa = xr[lane];
    float4 ca = cr[lane];
    float4 xb = xr[lane + 32];
    float4 cb = cr[lane + 32];

    float d0 = xa.x - ca.x, d1 = xa.y - ca.y, d2 = xa.z - ca.z, d3 = xa.w - ca.w;
    float e0 = xb.x - cb.x, e1 = xb.y - cb.y, e2 = xb.z - cb.z, e3 = xb.w - cb.w;
    float acc = d0*d0 + d1*d1 + d2*d2 + d3*d3
              + e0*e0 + e1*e1 + e2*e2 + e3*e3;

    #pragma unroll
    for (int off = 16; off > 0; off >>= 1)
        acc += __shfl_xor_sync(0xFFFFFFFFu, acc, off);

    if (lane == 0) {
        g_row_dist[row] = acc;
        __threadfence();                       // release row result
    }
    __syncthreads();

    // ---- last block to arrive performs the final reduction ----
    __shared__ bool am_last;
    if (tid == 0) {
        unsigned int c = atomicAdd(&g_done, 1u);
        am_last = (c == (unsigned int)(gridDim.x - 1));
    }
    __syncthreads();
    if (!am_last) return;

    __threadfence();                           // acquire all row results

    double dsum = 0.0;
    #pragma unroll
    for (int i = 0; i < B_ROWS / THREADS; i++) {   // 4 values per thread
        float v = g_row_dist[tid + i * THREADS];
        v = fminf(fmaxf(v, 1e-12f), 1e12f);
        dsum += (double)v;
    }

    #pragma unroll
    for (int off = 16; off > 0; off >>= 1)
        dsum += __shfl_xor_sync(0xFFFFFFFFu, dsum, off);

    __shared__ double s_warp[8];
    if (lane == 0) s_warp[warp] = dsum;
    __syncthreads();

    if (warp == 0) {
        double v = (lane < 8) ? s_warp[lane] : 0.0;
        #pragma unroll
        for (int off = 4; off > 0; off >>= 1)
            v += __shfl_xor_sync(0xFFFFFFFFu, v, off);
        if (lane == 0) {
            const double floor_term = (double)B_ROWS * (double)(C_CLS - 1) * 1e-12;
            out[0] = (float)((v + floor_term) / (double)B_ROWS);
            g_done = 0;                        // reset for next graph replay
        }
    }
}

extern "C" void kernel_launch(void* const* d_in, const int* in_sizes, int n_in,
                              void* d_out, int out_size) {
    // Identify inputs by element count (robust to ordering):
    //   x: 262144, labels: 1024, centers: 25600000
    const float* x       = nullptr;
    const void*  labels  = nullptr;
    const float* centers = nullptr;
    for (int i = 0; i < n_in; i++) {
        if (in_sizes[i] == B_ROWS * D_DIM)      x       = (const float*)d_in[i];
        else if (in_sizes[i] == B_ROWS)         labels  = d_in[i];
        else if (in_sizes[i] == C_CLS * D_DIM)  centers = (const float*)d_in[i];
    }
    float* out = (float*)d_out;

    center_loss_fused_kernel<<<BLOCKS, THREADS>>>(x, labels, centers, out);
}

// round 4
// speedup vs baseline: 1.2316x; 1.0257x over previous
#include <cuda_runtime.h>
#include <cuda_bf16.h>

// CenterLoss collapses analytically:
//   loss = ( sum_i clip(||x_i - c_{l_i}||^2, 1e-12, 1e12) + B*(C-1)*1e-12 ) / B
// Single kernel, single launch. Per-row squared distance -> fixed-point (2^32)
// integer atomic accumulation (deterministic, order-independent) -> the last
// block to finish writes the scalar output. No second reduction phase.

#define B_ROWS 1024
#define D_DIM  256
#define C_CLS  100000

#define RPW     4                        // rows per warp
#define WARPS   8
#define THREADS (WARPS * 32)             // 256
#define BLOCKS  (B_ROWS / (WARPS * RPW)) // 32

#define FP_SCALE 4294967296.0            // 2^32

static __device__ unsigned long long g_acc  = 0;  // fixed-point sum of row dists
static __device__ unsigned int       g_done = 0;  // block completion counter

__global__ void __launch_bounds__(THREADS)
center_loss_kernel(const float* __restrict__ x,
                   const void*  __restrict__ labels_raw,
                   const float* __restrict__ centers,
                   float* __restrict__ out) {
    const int tid  = threadIdx.x;
    const int lane = tid & 31;
    const int warp = tid >> 5;
    const int base = (blockIdx.x * WARPS + warp) * RPW;   // first row of this warp

    const int*       p32 = (const int*)labels_raw;
    const long long* p64 = (const long long*)labels_raw;

    // Speculative int32 label loads (proven dtype; issued in parallel with
    // the detection loads -> no extra memory round trip on the fast path).
    int lab32[RPW];
    #pragma unroll
    for (int r = 0; r < RPW; r++) lab32[r] = p32[base + r];

    // Dtype detection: first 32B viewed as 4 int64. Genuine int64 labels are
    // all in [0, C); int32 data viewed as int64 is lo|hi<<32 >= 2^32 unless
    // hi==0 -- 4 consecutive zero labels is effectively impossible.
    bool is64 = true;
    #pragma unroll
    for (int i = 0; i < 4; i++) {
        long long v = p64[i];
        if (v < 0 || v >= (long long)C_CLS) is64 = false;
    }

    long long lab[RPW];
    #pragma unroll
    for (int r = 0; r < RPW; r++) {
        long long l = is64 ? p64[base + r] : (long long)lab32[r];
        if (l < 0) l = 0;                       // never OOB even if detection wrong
        if (l >= C_CLS) l = C_CLS - 1;
        lab[r] = l;
    }

    // Gather: 4 rows x (2 float4 from x + 2 float4 from centers) per lane
    // = 16 independent LDG.128 in flight.
    float4 xa[RPW][2], ca[RPW][2];
    #pragma unroll
    for (int r = 0; r < RPW; r++) {
        const float4* xr = (const float4*)(x + (size_t)(base + r) * D_DIM);
        const float4* cr = (const float4*)(centers + (size_t)lab[r] * D_DIM);
        xa[r][0] = xr[lane];       xa[r][1] = xr[lane + 32];
        ca[r][0] = cr[lane];       ca[r][1] = cr[lane + 32];
    }

    // Per-row squared distance + warp reduction (4 independent trees, ILP).
    float s[RPW];
    #pragma unroll
    for (int r = 0; r < RPW; r++) {
        float d0 = xa[r][0].x - ca[r][0].x, d1 = xa[r][0].y - ca[r][0].y;
        float d2 = xa[r][0].z - ca[r][0].z, d3 = xa[r][0].w - ca[r][0].w;
        float e0 = xa[r][1].x - ca[r][1].x, e1 = xa[r][1].y - ca[r][1].y;
        float e2 = xa[r][1].z - ca[r][1].z, e3 = xa[r][1].w - ca[r][1].w;
        s[r] = d0*d0 + d1*d1 + d2*d2 + d3*d3
             + e0*e0 + e1*e1 + e2*e2 + e3*e3;
    }
    #pragma unroll
    for (int off = 16; off > 0; off >>= 1) {
        #pragma unroll
        for (int r = 0; r < RPW; r++)
            s[r] += __shfl_xor_sync(0xFFFFFFFFu, s[r], off);
    }

    // Quantize (clamp per row first, exactly as the reference) and combine.
    __shared__ unsigned long long s_acc[WARPS];
    if (lane == 0) {
        unsigned long long q = 0;
        #pragma unroll
        for (int r = 0; r < RPW; r++) {
            float v = fminf(fmaxf(s[r], 1e-12f), 1e12f);
            q += (unsigned long long)__double2ll_rn((double)v * FP_SCALE);
        }
        s_acc[warp] = q;
    }
    __syncthreads();

    if (tid == 0) {
        unsigned long long total = 0;
        #pragma unroll
        for (int w = 0; w < WARPS; w++) total += s_acc[w];
        atomicAdd(&g_acc, total);
        __threadfence();                        // release my contribution
        unsigned int c = atomicAdd(&g_done, 1u);
        if (c == (unsigned int)(BLOCKS - 1)) {
            __threadfence();                    // acquire all contributions
            unsigned long long tot = atomicAdd(&g_acc, 0ULL);  // coherent read
            const double floor_term = (double)B_ROWS * (double)(C_CLS - 1) * 1e-12;
            double sum = (double)tot / FP_SCALE;
            out[0] = (float)((sum + floor_term) / (double)B_ROWS);
            g_acc  = 0;                         // reset for next graph replay
            g_done = 0;
        }
    }
}

extern "C" void kernel_launch(void* const* d_in, const int* in_sizes, int n_in,
                              void* d_out, int out_size) {
    // Identify inputs by element count (robust to ordering):
    //   x: 262144, labels: 1024, centers: 25600000
    const float* x       = nullptr;
    const void*  labels  = nullptr;
    const float* centers = nullptr;
    for (int i = 0; i < n_in; i++) {
        if (in_sizes[i] == B_ROWS * D_DIM)      x       = (const float*)d_in[i];
        else if (in_sizes[i] == B_ROWS)         labels  = d_in[i];
        else if (in_sizes[i] == C_CLS * D_DIM)  centers = (const float*)d_in[i];
    }
    float* out = (float*)d_out;

    center_loss_kernel<<<BLOCKS, THREADS>>>(x, labels, centers, out);
}

// round 6
// speedup vs baseline: 1.3035x; 1.0584x over previous
#include <cuda_runtime.h>
#include <cuda_bf16.h>

// CenterLoss collapses analytically:
//   loss = ( sum_i clip(||x_i - c_{l_i}||^2, 1e-12, 1e12) + B*(C-1)*1e-12 ) / B
// Single kernel, single launch, ONE atomic as both accumulator and completion
// counter: bits [0,48) = fixed-point (2^24) sum, bits [48,64) = warp counter
// (16 bits, counts to 65535 >> 256 warps; R5 bug was a 7-bit field).
// The warp whose atomicAdd return shows count==WARPS_TOTAL-1 owns the full sum
// (old + own contribution) -- no fences, no syncthreads, no second phase.

#define B_ROWS 1024
#define D_DIM  256
#define C_CLS  100000

#define RPW     4                         // rows per warp
#define WARPS   8
#define THREADS (WARPS * 32)              // 256
#define BLOCKS  (B_ROWS / (WARPS * RPW))  // 32
#define WARPS_TOTAL (BLOCKS * WARPS)      // 256

#define FP_SCALE_F 16777216.0f            // 2^24
#define FP_SCALE_D 16777216.0
#define CNT_SHIFT  48
#define SUM_MASK   ((1ULL << CNT_SHIFT) - 1ULL)

static __device__ unsigned long long g_acc = 0;  // sum + counter, self-resetting

__global__ void __launch_bounds__(THREADS)
center_loss_kernel(const float* __restrict__ x,
                   const void*  __restrict__ labels_raw,
                   const float* __restrict__ centers,
                   float* __restrict__ out) {
    const int tid  = threadIdx.x;
    const int lane = tid & 31;
    const int warp = tid >> 5;
    const int base = (blockIdx.x * WARPS + warp) * RPW;   // first row of this warp

    const int*       p32 = (const int*)labels_raw;
    const long long* p64 = (const long long*)labels_raw;

    // Speculative int32 label loads (actual dtype; issued in parallel with
    // the detection loads so the fast path costs no extra round trip).
    int lab32[RPW];
    #pragma unroll
    for (int r = 0; r < RPW; r++) lab32[r] = p32[base + r];

    // Dtype detection: first 32B viewed as 4 int64. Genuine int64 labels are
    // all in [0, C); int32 data viewed as int64 is lo|hi<<32 >= 2^32 unless
    // hi==0 -- four consecutive zero labels is effectively impossible.
    bool is64 = true;
    #pragma unroll
    for (int i = 0; i < 4; i++) {
        long long v = p64[i];
        if (v < 0 || v >= (long long)C_CLS) is64 = false;
    }

    long long lab[RPW];
    #pragma unroll
    for (int r = 0; r < RPW; r++) {
        long long l = is64 ? p64[base + r] : (long long)lab32[r];
        if (l < 0) l = 0;                       // never OOB even if detection wrong
        if (l >= C_CLS) l = C_CLS - 1;
        lab[r] = l;
    }

    // Gather: 4 rows x (2 float4 from x + 2 float4 from centers) per lane.
    float4 xa[RPW][2], ca[RPW][2];
    #pragma unroll
    for (int r = 0; r < RPW; r++) {
        const float4* xr = (const float4*)(x + (size_t)(base + r) * D_DIM);
        const float4* cr = (const float4*)(centers + (size_t)lab[r] * D_DIM);
        xa[r][0] = xr[lane];       xa[r][1] = xr[lane + 32];
        ca[r][0] = cr[lane];       ca[r][1] = cr[lane + 32];
    }

    // Per-row squared distance + warp reduction (4 independent trees, ILP).
    float s[RPW];
    #pragma unroll
    for (int r = 0; r < RPW; r++) {
        float d0 = xa[r][0].x - ca[r][0].x, d1 = xa[r][0].y - ca[r][0].y;
        float d2 = xa[r][0].z - ca[r][0].z, d3 = xa[r][0].w - ca[r][0].w;
        float e0 = xa[r][1].x - ca[r][1].x, e1 = xa[r][1].y - ca[r][1].y;
        float e2 = xa[r][1].z - ca[r][1].z, e3 = xa[r][1].w - ca[r][1].w;
        s[r] = d0*d0 + d1*d1 + d2*d2 + d3*d3
             + e0*e0 + e1*e1 + e2*e2 + e3*e3;
    }
    #pragma unroll
    for (int off = 16; off > 0; off >>= 1) {
        #pragma unroll
        for (int r = 0; r < RPW; r++)
            s[r] += __shfl_xor_sync(0xFFFFFFFFu, s[r], off);
    }

    // Lane 0: clamp per row (faithful to the reference), quantize in fp32,
    // and fold counter + sum into ONE atomic. The returned old value is the
    // synchronization: count==WARPS_TOTAL-1 means every other warp's add has
    // already landed, so old+mine is the complete sum.
    if (lane == 0) {
        unsigned long long q = 0;
        #pragma unroll
        for (int r = 0; r < RPW; r++) {
            float v = fminf(fmaxf(s[r], 1e-12f), 1e12f);
            q += __float2ull_rn(v * FP_SCALE_F);
        }
        unsigned long long contrib = (1ULL << CNT_SHIFT) + q;
        unsigned long long old = atomicAdd(&g_acc, contrib);
        if ((old >> CNT_SHIFT) == (unsigned long long)(WARPS_TOTAL - 1)) {
            unsigned long long tot = (old + contrib) & SUM_MASK;
            const double floor_term = (double)B_ROWS * (double)(C_CLS - 1) * 1e-12;
            double sum = (double)tot / FP_SCALE_D;
            out[0] = (float)((sum + floor_term) / (double)B_ROWS);
            atomicExch(&g_acc, 0ULL);           // reset for next graph replay
        }
    }
}

extern "C" void kernel_launch(void* const* d_in, const int* in_sizes, int n_in,
                              void* d_out, int out_size) {
    // Identify inputs by element count (robust to ordering):
    //   x: 262144, labels: 1024, centers: 25600000
    const float* x       = nullptr;
    const void*  labels  = nullptr;
    const float* centers = nullptr;
    for (int i = 0; i < n_in; i++) {
        if (in_sizes[i] == B_ROWS * D_DIM)      x       = (const float*)d_in[i];
        else if (in_sizes[i] == B_ROWS)         labels  = d_in[i];
        else if (in_sizes[i] == C_CLS * D_DIM)  centers = (const float*)d_in[i];
    }
    float* out = (float*)d_out;

    center_loss_kernel<<<BLOCKS, THREADS>>>(x, labels, centers, out);
}

// round 7
// speedup vs baseline: 1.6262x; 1.2476x over previous
#include <cuda_runtime.h>
#include <cuda_bf16.h>

// CenterLoss collapses analytically:
//   loss = ( sum_i clip(||x_i - c_{l_i}||^2, 1e-12, 1e12) + B*(C-1)*1e-12 ) / B
// Single kernel, single launch. Per-warp squared distances -> per-block smem
// integer combine -> ONE packed global atomic per block (32 total):
// bits [0,48) = fixed-point (2^24) sum, bits [48,64) = block counter.
// The block whose atomicAdd return shows count==BLOCKS-1 owns the full sum
// (old + own contribution). No fences, no second phase, no re-reads --
// the sum travels inside the atomic value itself.

#define B_ROWS 1024
#define D_DIM  256
#define C_CLS  100000

#define RPW     4                         // rows per warp
#define WARPS   8
#define THREADS (WARPS * 32)              // 256
#define BLOCKS  (B_ROWS / (WARPS * RPW))  // 32

#define FP_SCALE_F 16777216.0f            // 2^24
#define FP_SCALE_D 16777216.0
#define CNT_SHIFT  48
#define SUM_MASK   ((1ULL << CNT_SHIFT) - 1ULL)

static __device__ unsigned long long g_acc = 0;  // sum + counter, self-resetting

__global__ void __launch_bounds__(THREADS)
center_loss_kernel(const float* __restrict__ x,
                   const void*  __restrict__ labels_raw,
                   const float* __restrict__ centers,
                   float* __restrict__ out) {
    const int tid  = threadIdx.x;
    const int lane = tid & 31;
    const int warp = tid >> 5;
    const int base = (blockIdx.x * WARPS + warp) * RPW;   // first row of this warp

    const int*       p32 = (const int*)labels_raw;
    const long long* p64 = (const long long*)labels_raw;

    // Speculative int32 label loads (actual dtype; issued in parallel with
    // the detection loads so the fast path costs no extra round trip).
    int lab32[RPW];
    #pragma unroll
    for (int r = 0; r < RPW; r++) lab32[r] = p32[base + r];

    // Dtype detection: first 32B viewed as 4 int64. Genuine int64 labels are
    // all in [0, C); int32 data viewed as int64 is lo|hi<<32 >= 2^32 unless
    // hi==0 -- four consecutive zero labels is effectively impossible.
    bool is64 = true;
    #pragma unroll
    for (int i = 0; i < 4; i++) {
        long long v = p64[i];
        if (v < 0 || v >= (long long)C_CLS) is64 = false;
    }

    long long lab[RPW];
    #pragma unroll
    for (int r = 0; r < RPW; r++) {
        long long l = is64 ? p64[base + r] : (long long)lab32[r];
        if (l < 0) l = 0;                       // never OOB even if detection wrong
        if (l >= C_CLS) l = C_CLS - 1;
        lab[r] = l;
    }

    // Gather: 4 rows x (2 float4 from x + 2 float4 from centers) per lane
    // = 16 independent LDG.128 in flight.
    float4 xa[RPW][2], ca[RPW][2];
    #pragma unroll
    for (int r = 0; r < RPW; r++) {
        const float4* xr = (const float4*)(x + (size_t)(base + r) * D_DIM);
        const float4* cr = (const float4*)(centers + (size_t)lab[r] * D_DIM);
        xa[r][0] = xr[lane];       xa[r][1] = xr[lane + 32];
        ca[r][0] = cr[lane];       ca[r][1] = cr[lane + 32];
    }

    // Per-row squared distance + warp reduction (4 independent trees, ILP).
    float s[RPW];
    #pragma unroll
    for (int r = 0; r < RPW; r++) {
        float d0 = xa[r][0].x - ca[r][0].x, d1 = xa[r][0].y - ca[r][0].y;
        float d2 = xa[r][0].z - ca[r][0].z, d3 = xa[r][0].w - ca[r][0].w;
        float e0 = xa[r][1].x - ca[r][1].x, e1 = xa[r][1].y - ca[r][1].y;
        float e2 = xa[r][1].z - ca[r][1].z, e3 = xa[r][1].w - ca[r][1].w;
        s[r] = d0*d0 + d1*d1 + d2*d2 + d3*d3
             + e0*e0 + e1*e1 + e2*e2 + e3*e3;
    }
    #pragma unroll
    for (int off = 16; off > 0; off >>= 1) {
        #pragma unroll
        for (int r = 0; r < RPW; r++)
            s[r] += __shfl_xor_sync(0xFFFFFFFFu, s[r], off);
    }

    // Per-warp quantize (clamp per row first, faithful to the reference).
    __shared__ unsigned long long s_q[WARPS];
    if (lane == 0) {
        unsigned long long q = 0;
        #pragma unroll
        for (int r = 0; r < RPW; r++) {
            float v = fminf(fmaxf(s[r], 1e-12f), 1e12f);
            q += __float2ull_rn(v * FP_SCALE_F);
        }
        s_q[warp] = q;
    }
    __syncthreads();

    // ONE packed global atomic per block. The returned old value is the
    // synchronization: count==BLOCKS-1 means every other block's add landed.
    if (tid == 0) {
        unsigned long long q = 0;
        #pragma unroll
        for (int w = 0; w < WARPS; w++) q += s_q[w];   // exact integer adds

        unsigned long long contrib = (1ULL << CNT_SHIFT) + q;
        unsigned long long old = atomicAdd(&g_acc, contrib);
        if ((old >> CNT_SHIFT) == (unsigned long long)(BLOCKS - 1)) {
            unsigned long long tot = (old + contrib) & SUM_MASK;
            const double floor_term = (double)B_ROWS * (double)(C_CLS - 1) * 1e-12;
            double sum = (double)tot / FP_SCALE_D;
            out[0] = (float)((sum + floor_term) / (double)B_ROWS);
            atomicExch(&g_acc, 0ULL);           // reset for next graph replay
        }
    }
}

extern "C" void kernel_launch(void* const* d_in, const int* in_sizes, int n_in,
                              void* d_out, int out_size) {
    // Identify inputs by element count (robust to ordering):
    //   x: 262144, labels: 1024, centers: 25600000
    const float* x       = nullptr;
    const void*  labels  = nullptr;
    const float* centers = nullptr;
    for (int i = 0; i < n_in; i++) {
        if (in_sizes[i] == B_ROWS * D_DIM)      x       = (const float*)d_in[i];
        else if (in_sizes[i] == B_ROWS)         labels  = d_in[i];
        else if (in_sizes[i] == C_CLS * D_DIM)  centers = (const float*)d_in[i];
    }
    float* out = (float*)d_out;

    center_loss_kernel<<<BLOCKS, THREADS>>>(x, labels, centers, out);
}